// round 7
// baseline (speedup 1.0000x reference)
#include <cuda_runtime.h>
#include <cstdint>

#define NJ 50
#define EDIM 192
#define NJP 56           // padded codes (4 js * 14)
#define ETSTRIDE 56      // floats per k-row of Et ([k][j] transpose, stride 56)
#define NWARP 6
#define NTHREADS 192
#define ROWS_PER_THREAD 6
#define ROWS_PER_WARP 48
#define ROWS_PER_BLOCK 288

__device__ double g_loss_sum;     // zero-init at module load
__device__ unsigned int g_done;

static __device__ __forceinline__ unsigned long long pack2(float lo, float hi) {
    unsigned long long r;
    asm("mov.b64 %0, {%1, %2};" : "=l"(r) : "f"(lo), "f"(hi));
    return r;
}
static __device__ __forceinline__ unsigned long long pack2s(float v) {
    unsigned long long r;
    asm("mov.b64 %0, {%1, %1};" : "=l"(r) : "f"(v));
    return r;
}
static __device__ __forceinline__ void unpack2(unsigned long long v, float& lo, float& hi) {
    asm("mov.b64 {%0, %1}, %2;" : "=f"(lo), "=f"(hi) : "l"(v));
}
// Packed dual fp32 FMA (FFMA2)
static __device__ __forceinline__ unsigned long long fma2(unsigned long long a,
                                                          unsigned long long b,
                                                          unsigned long long c) {
    unsigned long long d;
    asm("fma.rn.f32x2 %0, %1, %2, %3;" : "=l"(d) : "l"(a), "l"(b), "l"(c));
    return d;
}

// lane = (g<<2)|js : js in [0,4) code split (14 each, j = 14*js+jj), g in [0,8).
// Thread rows: base + g + 8*i, i=0..5 (6 rows/thread, 48 rows/warp).
// acc f32x2 packs a CODE PAIR -> e operand is a raw LDS.64 shared by 6 rows.
__global__ void __launch_bounds__(NTHREADS, 2) vq_kernel(
        const float* __restrict__ x, const float* __restrict__ e,
        float* __restrict__ out, int n) {
    __shared__ __align__(8) float Et[EDIM * ETSTRIDE];  // Et[k*56 + j] = e[j][k], j>=50 zero
    __shared__ float see[NJP];
    __shared__ int   bjsh[ROWS_PER_BLOCK];
    __shared__ float wred[NWARP];

    const int tid = threadIdx.x;
    const int wid = tid >> 5;
    const int lane = tid & 31;
    const int js = lane & 3;
    const int g = lane >> 2;

    // ---- init: zero Et, fill transpose, see (+inf pads) ----
    for (int i = tid; i < EDIM * ETSTRIDE; i += NTHREADS) Et[i] = 0.f;
    __syncthreads();
    for (int i = tid; i < NJ * EDIM; i += NTHREADS) {
        int j = i / EDIM, k = i - j * EDIM;        // e[j][k] coalesced read
        Et[k * ETSTRIDE + j] = e[i];
    }
    if (tid < NJP) {
        float s = 3.402823466e38f;
        if (tid < NJ) {
            s = 0.f;
            const float* ej = e + (size_t)tid * EDIM;
            #pragma unroll 4
            for (int k = 0; k < EDIM; ++k) { float v = __ldg(ej + k); s = fmaf(v, v, s); }
        }
        see[tid] = s;
    }
    __syncthreads();

    const int tile_base = blockIdx.x * ROWS_PER_BLOCK;
    const int warpbase = wid * ROWS_PER_WARP;
    int rows[ROWS_PER_THREAD];
    #pragma unroll
    for (int i = 0; i < ROWS_PER_THREAD; ++i) {
        int r = tile_base + warpbase + g + 8 * i;
        rows[i] = (r < n) ? r : (n - 1);
    }

    // ---- accumulate 6 rows x 7 code-pairs + per-row ||x||^2 (R2's exact chain,
    //      packed as row-pair f32x2: each f32x2 lane is one row's own chain) ----
    unsigned long long acc[ROWS_PER_THREAD][7];
    unsigned long long ss0[3], ss1[3];             // row-pairs (0,1),(2,3),(4,5)
    #pragma unroll
    for (int i = 0; i < ROWS_PER_THREAD; ++i) {
        #pragma unroll
        for (int p = 0; p < 7; ++p) acc[i][p] = 0ULL;
    }
    #pragma unroll
    for (int p = 0; p < 3; ++p) { ss0[p] = 0ULL; ss1[p] = 0ULL; }

    const float4* x4 = reinterpret_cast<const float4*>(x);
    const int ebase = 14 * js;

    #pragma unroll 1
    for (int kq = 0; kq < EDIM / 4; ++kq) {
        float4 xv[ROWS_PER_THREAD];
        #pragma unroll
        for (int i = 0; i < ROWS_PER_THREAD; ++i)
            xv[i] = __ldg(x4 + (size_t)rows[i] * 48 + kq);

        #pragma unroll
        for (int c = 0; c < 4; ++c) {
            const int k = kq * 4 + c;
            const unsigned long long* ep =
                reinterpret_cast<const unsigned long long*>(&Et[k * ETSTRIDE + ebase]);
            float a0, a1, a2, a3, a4, a5;
            if (c == 0)      { a0=xv[0].x; a1=xv[1].x; a2=xv[2].x; a3=xv[3].x; a4=xv[4].x; a5=xv[5].x; }
            else if (c == 1) { a0=xv[0].y; a1=xv[1].y; a2=xv[2].y; a3=xv[3].y; a4=xv[4].y; a5=xv[5].y; }
            else if (c == 2) { a0=xv[0].z; a1=xv[1].z; a2=xv[2].z; a3=xv[3].z; a4=xv[4].z; a5=xv[5].z; }
            else             { a0=xv[0].w; a1=xv[1].w; a2=xv[2].w; a3=xv[3].w; a4=xv[4].w; a5=xv[5].w; }
            // ||x||^2: comps x,z -> ss0 ; y,w -> ss1 (per-row order == R2 chain)
            const unsigned long long q0 = pack2(a0, a1);
            const unsigned long long q1 = pack2(a2, a3);
            const unsigned long long q2 = pack2(a4, a5);
            if ((c & 1) == 0) {
                ss0[0] = fma2(q0, q0, ss0[0]);
                ss0[1] = fma2(q1, q1, ss0[1]);
                ss0[2] = fma2(q2, q2, ss0[2]);
            } else {
                ss1[0] = fma2(q0, q0, ss1[0]);
                ss1[1] = fma2(q1, q1, ss1[1]);
                ss1[2] = fma2(q2, q2, ss1[2]);
            }
            unsigned long long xp[ROWS_PER_THREAD];
            xp[0] = pack2s(a0); xp[1] = pack2s(a1); xp[2] = pack2s(a2);
            xp[3] = pack2s(a3); xp[4] = pack2s(a4); xp[5] = pack2s(a5);
            #pragma unroll
            for (int p = 0; p < 7; ++p) {
                const unsigned long long ev = ep[p];   // LDS.64: codes (2p, 2p+1)
                #pragma unroll
                for (int i = 0; i < ROWS_PER_THREAD; ++i)
                    acc[i][p] = fma2(xp[i], ev, acc[i][p]);
            }
        }
    }

    // ---- per-thread argmin (exact R2 compare), then combine over 4 js-lanes ----
    #pragma unroll
    for (int i = 0; i < ROWS_PER_THREAD; ++i) {
        float s0lo, s0hi, s1lo, s1hi;
        unpack2(ss0[i >> 1], s0lo, s0hi);
        unpack2(ss1[i >> 1], s1lo, s1hi);
        const float sxx = (i & 1) ? (s0hi + s1hi) : (s0lo + s1lo);
        float v = 3.402823466e38f;
        int jx = 0;
        #pragma unroll
        for (int p = 0; p < 7; ++p) {
            float dlo, dhi;
            unpack2(acc[i][p], dlo, dhi);
            const int j = ebase + 2 * p;
            float mlo = __fsub_rn(__fadd_rn(sxx, see[j]),     2.0f * dlo);
            float mhi = __fsub_rn(__fadd_rn(sxx, see[j + 1]), 2.0f * dhi);
            if (mlo < v) { v = mlo; jx = j; }
            if (mhi < v) { v = mhi; jx = j + 1; }
        }
        #pragma unroll
        for (int mask = 1; mask <= 2; mask <<= 1) {
            float ov = __shfl_xor_sync(0xffffffffu, v, mask);
            int   oj = __shfl_xor_sync(0xffffffffu, jx, mask);
            if (ov < v || (ov == v && oj < jx)) { v = ov; jx = oj; }
        }
        const int grow = tile_base + warpbase + g + 8 * i;
        if (js == 0) {
            bjsh[warpbase + g + 8 * i] = jx;
            if (grow < n) out[(size_t)n * EDIM + grow] = (float)jx;
        }
    }
    __syncwarp();

    // ---- phase 2: warp-cooperative coalesced straight-through write + loss ----
    float lsum = 0.f;
    const float4* e4 = reinterpret_cast<const float4*>(e);
    float4* o4 = reinterpret_cast<float4*>(out);
    #pragma unroll 4
    for (int it = 0; it < (ROWS_PER_WARP * 48) / 32; ++it) {   // 72 iters
        const int idx = it * 32 + lane;
        const int rl = idx / 48, c4 = idx - rl * 48;
        const int grow = tile_base + warpbase + rl;
        if (grow < n) {
            const int bj = bjsh[warpbase + rl];
            const float4 xq = __ldg(x4 + (size_t)grow * 48 + c4);
            const float4 qq = __ldg(e4 + (size_t)bj * 48 + c4);
            float dx = __fsub_rn(qq.x, xq.x), dy = __fsub_rn(qq.y, xq.y);
            float dz = __fsub_rn(qq.z, xq.z), dw = __fsub_rn(qq.w, xq.w);
            lsum = fmaf(dx, dx, lsum); lsum = fmaf(dy, dy, lsum);
            lsum = fmaf(dz, dz, lsum); lsum = fmaf(dw, dw, lsum);
            float4 o;
            o.x = __fadd_rn(xq.x, dx); o.y = __fadd_rn(xq.y, dy);
            o.z = __fadd_rn(xq.z, dz); o.w = __fadd_rn(xq.w, dw);
            o4[(size_t)grow * 48 + c4] = o;
        }
    }

    // ---- loss reduction + single-kernel finalize ----
    #pragma unroll
    for (int off = 16; off > 0; off >>= 1)
        lsum += __shfl_down_sync(0xffffffffu, lsum, off);
    if (lane == 0) wred[wid] = lsum;
    __syncthreads();
    if (tid == 0) {
        float bs = 0.f;
        #pragma unroll
        for (int w = 0; w < NWARP; ++w) bs += wred[w];
        atomicAdd(&g_loss_sum, (double)bs);
        __threadfence();
        unsigned int prev = atomicAdd(&g_done, 1u);
        if (prev == gridDim.x - 1) {
            __threadfence();
            double total = atomicAdd(&g_loss_sum, 0.0);
            double mean = total / ((double)n * (double)EDIM);
            out[(size_t)n * EDIM + n]     = (float)(1.25 * mean);  // (1+BETA)*mean
            out[(size_t)n * EDIM + n + 1] = 0.0f;                  // contrastloss
            g_loss_sum = 0.0;
            g_done = 0u;
            __threadfence();
        }
    }
}

extern "C" void kernel_launch(void* const* d_in, const int* in_sizes, int n_in,
                              void* d_out, int out_size) {
    (void)n_in; (void)out_size;
    const float* x = (const float*)d_in[0];   // [N, 192] fp32
    const float* e = (const float*)d_in[1];   // [50, 192] fp32
    float* out = (float*)d_out;               // [N*192 | N | 1 | 1] fp32
    const int n = in_sizes[0] / EDIM;

    const int blocks = (n + ROWS_PER_BLOCK - 1) / ROWS_PER_BLOCK;
    vq_kernel<<<blocks, NTHREADS>>>(x, e, out, n);
}